// round 1
// baseline (speedup 1.0000x reference)
#include <cuda_runtime.h>
#include <cstdint>

#define SEQ     256
#define BATCH   512
#define IN_DIM  256
#define HDIM    8
#define DIN     264          // IN_DIM + HDIM
#define NROWS   (SEQ * BATCH)

// Scratch: pre-activations from the input projection (bias folded in).
// Layout: zx[(t*BATCH + b)*32 + (g*8 + q)]
__device__ float g_zx[(size_t)NROWS * 32];

__device__ __forceinline__ void ffma2(unsigned long long &d,
                                      unsigned long long a,
                                      unsigned long long b) {
    asm("fma.rn.f32x2 %0, %1, %2, %0;" : "+l"(d) : "l"(a), "l"(b));
}

__device__ __forceinline__ float tanh_approx(float x) {
    float y;
    asm("tanh.approx.f32 %0, %1;" : "=f"(y) : "f"(x));
    return y;
}

// ---------------------------------------------------------------------------
// Kernel A: zx = x @ Wx.T + b for all 4 gates, all (t, b) rows in parallel.
// Grid: 1024 blocks x 256 threads = 8192 warps; 16 rows per warp.
// lane = output index o in [0,32): g = o>>3 (gate), q = o&7 (qubit).
// Weights for this lane's output row held in registers per 64-wide k-chunk;
// x is broadcast-loaded (all lanes same address -> 1 transaction).
// ---------------------------------------------------------------------------
__global__ void __launch_bounds__(256)
qlstm_gemm(const float* __restrict__ x,
           const float* __restrict__ Wf, const float* __restrict__ bf,
           const float* __restrict__ Wi, const float* __restrict__ bi,
           const float* __restrict__ Wu, const float* __restrict__ bu,
           const float* __restrict__ Wo, const float* __restrict__ bo)
{
    const int lane = threadIdx.x & 31;
    const int warp = blockIdx.x * (blockDim.x >> 5) + (threadIdx.x >> 5);
    const int g = lane >> 3, q = lane & 7;

    const float* W  = (g == 0 ? Wf : (g == 1 ? Wi : (g == 2 ? Wu : Wo))) + q * DIN;
    const float* bp = (g == 0 ? bf : (g == 1 ? bi : (g == 2 ? bu : bo)));
    const float bias = bp[q];

    const int row0 = warp * 16;   // 8192 warps * 16 rows = 131072 = NROWS exactly

    unsigned long long acc2[16];
#pragma unroll
    for (int r = 0; r < 16; r++) acc2[r] = 0ULL;

#pragma unroll 1
    for (int kc = 0; kc < 4; kc++) {
        // Load this lane's 64 weights for the k-chunk (DIN=264 floats/row -> 16B aligned)
        unsigned long long w2[32];
        const ulonglong2* wp = reinterpret_cast<const ulonglong2*>(W + kc * 64);
#pragma unroll
        for (int j = 0; j < 16; j++) {
            ulonglong2 wv = wp[j];
            w2[2 * j]     = wv.x;   // packs (W[4j], W[4j+1])
            w2[2 * j + 1] = wv.y;   // packs (W[4j+2], W[4j+3])
        }
#pragma unroll
        for (int r = 0; r < 16; r++) {
            const ulonglong2* xp = reinterpret_cast<const ulonglong2*>(
                x + (size_t)(row0 + r) * IN_DIM + kc * 64);
#pragma unroll
            for (int j = 0; j < 16; j++) {
                ulonglong2 xv = xp[j];              // broadcast across lanes
                ffma2(acc2[r], xv.x, w2[2 * j]);
                ffma2(acc2[r], xv.y, w2[2 * j + 1]);
            }
        }
    }

#pragma unroll
    for (int r = 0; r < 16; r++) {
        float2 p = *reinterpret_cast<float2*>(&acc2[r]);
        g_zx[(size_t)(row0 + r) * 32 + lane] = p.x + p.y + bias;
    }
}

// ---------------------------------------------------------------------------
// Kernel B: the 256-step recurrence. One warp per batch element.
// lane o = g*8 + q. Each lane holds the 8 recurrent weights for its output,
// plus the replicated cell state for its qubit q.
// ---------------------------------------------------------------------------
__global__ void __launch_bounds__(128)
qlstm_recur(const float* __restrict__ Wf, const float* __restrict__ Wi,
            const float* __restrict__ Wu, const float* __restrict__ Wo,
            const float* __restrict__ pf, const float* __restrict__ pi_,
            const float* __restrict__ pu, const float* __restrict__ po,
            float* __restrict__ out)
{
    const unsigned FULL = 0xFFFFFFFFu;
    const int lane = threadIdx.x & 31;
    const int b    = blockIdx.x * (blockDim.x >> 5) + (threadIdx.x >> 5); // batch
    const int g = lane >> 3, q = lane & 7;

    const float* W = (g == 0 ? Wf : (g == 1 ? Wi : (g == 2 ? Wu : Wo))) + q * DIN + IN_DIM;
    const float* p = (g == 0 ? pf : (g == 1 ? pi_ : (g == 2 ? pu : po)));

    float Whr[8];
#pragma unroll
    for (int j = 0; j < 8; j++) Whr[j] = W[j];
    const float ctheta = __cosf(p[q]);

    float* stacked = out;                                   // (SEQ, BATCH, H)
    float* hx_out  = out + (size_t)SEQ * BATCH * HDIM;      // (BATCH, H)
    float* cx_out  = hx_out + (size_t)BATCH * HDIM;         // (BATCH, H)

    const float* zp = g_zx + (size_t)b * 32 + lane;
    const size_t zstride = (size_t)BATCH * 32;

    float hq = 0.f, cq = 0.f;           // state for qubit q (replicated x4 gates)
    float zcur = zp[0];

#pragma unroll 1
    for (int t = 0; t < SEQ; t++) {
        // prefetch next step's pre-activation (hides L2 latency behind compute)
        float znext = (t + 1 < SEQ) ? zp[(size_t)(t + 1) * zstride] : 0.f;

        // recurrent dot: z += sum_j h[j] * Wh[o][j]; h[j] lives on lane j
        float z = zcur;
#pragma unroll
        for (int j = 0; j < 8; j++)
            z = fmaf(__shfl_sync(FULL, hq, j), Whr[j], z);

        // qgate: cumprod over qubits of cos(z)*cos(theta)
        float cv = __cosf(z) * ctheta;
#pragma unroll
        for (int d = 1; d < 8; d <<= 1) {
            float v = __shfl_up_sync(FULL, cv, d, 8);   // scan within 8-lane group
            if (q >= d) cv *= v;
        }

        // gate nonlinearity, branch-free: sigmoid(x) = 0.5*tanh(0.5x) + 0.5
        float arg = (g == 2) ? cv : 0.5f * cv;
        float th  = tanh_approx(arg);
        float a   = (g == 2) ? th : fmaf(0.5f, th, 0.5f);

        // gather f/i/u/o for this lane's qubit
        float fv = __shfl_sync(FULL, a, q);
        float iv = __shfl_sync(FULL, a, 8 + q);
        float uv = __shfl_sync(FULL, a, 16 + q);
        float ov = __shfl_sync(FULL, a, 24 + q);

        cq = fmaf(fv, cq, iv * uv);
        hq = ov * tanh_approx(cq);

        if (lane < 8)
            stacked[((size_t)t * BATCH + b) * HDIM + q] = hq;

        zcur = znext;
    }

    if (lane < 8) {
        hx_out[(size_t)b * HDIM + q] = hq;
        cx_out[(size_t)b * HDIM + q] = cq;
    }
}

extern "C" void kernel_launch(void* const* d_in, const int* in_sizes, int n_in,
                              void* d_out, int out_size) {
    const float* inputs = (const float*)d_in[0];
    const float* Wf = (const float*)d_in[1];  const float* bf = (const float*)d_in[2];
    const float* Wi = (const float*)d_in[3];  const float* bi = (const float*)d_in[4];
    const float* Wu = (const float*)d_in[5];  const float* bu = (const float*)d_in[6];
    const float* Wo = (const float*)d_in[7];  const float* bo = (const float*)d_in[8];
    const float* pf  = (const float*)d_in[9];
    const float* pi_ = (const float*)d_in[10];
    const float* pu  = (const float*)d_in[11];
    const float* po  = (const float*)d_in[12];
    float* out = (float*)d_out;

    // Kernel A: 8192 warps x 16 rows = 131072 (t,b) rows
    qlstm_gemm<<<1024, 256>>>(inputs, Wf, bf, Wi, bi, Wu, bu, Wo, bo);
    // Kernel B: 512 warps = 512 batch elements
    qlstm_recur<<<128, 128>>>(Wf, Wi, Wu, Wo, pf, pi_, pu, po, out);
}

// round 2
// speedup vs baseline: 1.3239x; 1.3239x over previous
#include <cuda_runtime.h>
#include <cstdint>

#define SEQ     256
#define BATCH   512
#define IN_DIM  256
#define HDIM    8
#define DIN     264          // IN_DIM + HDIM
#define NROWS   (SEQ * BATCH)

// Scratch: pre-activations from the input projection (bias folded in).
// Layout: zx[(t*BATCH + b)*32 + (g*8 + q)]
__device__ float g_zx[(size_t)NROWS * 32];

typedef unsigned long long ull;

__device__ __forceinline__ void ffma2(ull &d, ull a, ull b) {
    asm("fma.rn.f32x2 %0, %1, %2, %0;" : "+l"(d) : "l"(a), "l"(b));
}

__device__ __forceinline__ float tanh_approx(float x) {
    float y;
    asm("tanh.approx.f32 %0, %1;" : "=f"(y) : "f"(x));
    return y;
}

__device__ __forceinline__ void cpasync16(void* dst, const void* src) {
    unsigned ds = (unsigned)__cvta_generic_to_shared(dst);
    asm volatile("cp.async.cg.shared.global [%0], [%1], 16;" :: "r"(ds), "l"(src));
}
__device__ __forceinline__ void cp_commit() {
    asm volatile("cp.async.commit_group;");
}
template <int N>
__device__ __forceinline__ void cp_wait() {
    asm volatile("cp.async.wait_group %0;" :: "n"(N));
}

// ---------------------------------------------------------------------------
// Kernel A: zx = x @ Wx.T + b (x-part of all 4 gate projections), all rows.
//
// Block = 256 threads (8 warps), 64 rows/block, grid = 2048.
// Warp w handles tile rows [8w, 8w+8). Lane: half = lane>>4 picks rows
// {8w + 4*half + r, r<4}; o16 = lane&15 picks outputs {o16, o16+16}.
// x flows GMEM -> smem (cp.async double buffer, XOR-swizzled) -> broadcast
// LDS.128; each 16B x read feeds 4 FFMA2 (2 outputs x 2 packed pairs).
// All 32 weight rows (x-part, 32KB) staged in smem once per block.
// ---------------------------------------------------------------------------
#define KCH    32
#define NCHUNK 8

__global__ void __launch_bounds__(256)
qlstm_gemm(const float* __restrict__ x,
           const float* __restrict__ Wf, const float* __restrict__ bf,
           const float* __restrict__ Wi, const float* __restrict__ bi,
           const float* __restrict__ Wu, const float* __restrict__ bu,
           const float* __restrict__ Wo, const float* __restrict__ bo)
{
    __shared__ float w_s[32 * 256];       // 32KB: weight x-part, row-major
    __shared__ float xs[2][64 * 32];      // 16KB: x tile, double buffered

    const int tid  = threadIdx.x;
    const int lane = tid & 31, warp = tid >> 5;
    const int half = lane >> 4, o16 = lane & 15;
    const int oA = o16, oB = o16 + 16;
    const int row0   = blockIdx.x * 64;
    const int tlRow0 = warp * 8 + half * 4;

    // Stage W x-part into smem: 2048 float4s, 8 per thread, coalesced per row.
    #pragma unroll
    for (int i = 0; i < 8; i++) {
        int idx = tid + 256 * i;              // float4 slot 0..2047
        int o = idx >> 6, j = idx & 63;       // o: output row, j: float4 within row
        int g = o >> 3, q = o & 7;
        const float* base = (g == 0 ? Wf : (g == 1 ? Wi : (g == 2 ? Wu : Wo)));
        cpasync16(&w_s[o * 256 + j * 4], base + q * DIN + j * 4);
    }

    // x chunk loader: 64 rows x 32 floats = 512 float4s, 2 per thread.
    auto load_x = [&](int kc, int buf) {
        #pragma unroll
        for (int i = 0; i < 2; i++) {
            int f = tid + 256 * i;            // float4 slot 0..511
            int r = f >> 3, j = f & 7;
            int jsw = j ^ (r & 7);            // xor swizzle: kills LDS bank conflicts
            cpasync16(&xs[buf][r * 32 + jsw * 4],
                      x + (size_t)(row0 + r) * IN_DIM + kc * KCH + j * 4);
        }
    };

    load_x(0, 0);
    cp_commit();                               // group: {W, x-chunk0}

    ull accA[4], accB[4];
    #pragma unroll
    for (int r = 0; r < 4; r++) { accA[r] = 0ULL; accB[r] = 0ULL; }

    #pragma unroll 1
    for (int kc = 0; kc < NCHUNK; kc++) {
        if (kc < NCHUNK - 1) { load_x(kc + 1, (kc + 1) & 1); cp_commit(); }
        if (kc < NCHUNK - 1) cp_wait<1>(); else cp_wait<0>();
        __syncthreads();

        // Per-chunk weights for both outputs: 16 ull each (broadcast LDS).
        ull wA[16], wB[16];
        {
            const ulonglong2* wpA = reinterpret_cast<const ulonglong2*>(&w_s[oA * 256 + kc * KCH]);
            const ulonglong2* wpB = reinterpret_cast<const ulonglong2*>(&w_s[oB * 256 + kc * KCH]);
            #pragma unroll
            for (int j = 0; j < 8; j++) {
                ulonglong2 a = wpA[j]; wA[2*j] = a.x; wA[2*j+1] = a.y;
                ulonglong2 b = wpB[j]; wB[2*j] = b.x; wB[2*j+1] = b.y;
            }
        }

        const float* xb = xs[kc & 1];
        #pragma unroll
        for (int r = 0; r < 4; r++) {
            int rl = tlRow0 + r;
            const float* xrow = xb + rl * 32;
            int sw = rl & 7;
            #pragma unroll
            for (int j = 0; j < 8; j++) {
                ulonglong2 xv = *reinterpret_cast<const ulonglong2*>(xrow + ((j ^ sw) * 4));
                ffma2(accA[r], xv.x, wA[2*j]); ffma2(accA[r], xv.y, wA[2*j+1]);
                ffma2(accB[r], xv.x, wB[2*j]); ffma2(accB[r], xv.y, wB[2*j+1]);
            }
        }
        __syncthreads();   // everyone done with buf (kc&1) before it's refilled
    }

    const float biasA = (oA < 8)  ? bf[oA]      : bi[oA - 8];
    const float biasB = (oB < 24) ? bu[oB - 16] : bo[oB - 24];

    #pragma unroll
    for (int r = 0; r < 4; r++) {
        int grow = row0 + tlRow0 + r;
        float2 pa = *reinterpret_cast<float2*>(&accA[r]);
        float2 pb = *reinterpret_cast<float2*>(&accB[r]);
        g_zx[(size_t)grow * 32 + oA] = pa.x + pa.y + biasA;
        g_zx[(size_t)grow * 32 + oB] = pb.x + pb.y + biasB;
    }
}

// ---------------------------------------------------------------------------
// Kernel B: the 256-step recurrence. One warp per batch element.
// lane o = g*8 + q. Every lane keeps ALL 8 h values in registers, so the
// recurrent dot is a pure 8-FMA chain (no shfl on the critical path there).
// Shfls that remain: 3-deep cumprod scan, 4 independent gate gathers,
// 8 independent end-of-step h broadcasts.
// ---------------------------------------------------------------------------
__global__ void __launch_bounds__(128)
qlstm_recur(const float* __restrict__ Wf, const float* __restrict__ Wi,
            const float* __restrict__ Wu, const float* __restrict__ Wo,
            const float* __restrict__ pf, const float* __restrict__ pi_,
            const float* __restrict__ pu, const float* __restrict__ po,
            float* __restrict__ out)
{
    const unsigned FULL = 0xFFFFFFFFu;
    const int lane = threadIdx.x & 31;
    const int b    = blockIdx.x * (blockDim.x >> 5) + (threadIdx.x >> 5);
    const int g = lane >> 3, q = lane & 7;

    const float* W = (g == 0 ? Wf : (g == 1 ? Wi : (g == 2 ? Wu : Wo))) + q * DIN + IN_DIM;
    const float* p = (g == 0 ? pf : (g == 1 ? pi_ : (g == 2 ? pu : po)));

    float Whr[8];
    #pragma unroll
    for (int j = 0; j < 8; j++) Whr[j] = W[j];
    const float ctheta = __cosf(p[q]);

    float* stacked = out;
    float* hx_out  = out + (size_t)SEQ * BATCH * HDIM;
    float* cx_out  = hx_out + (size_t)BATCH * HDIM;

    const float* zp = g_zx + (size_t)b * 32 + lane;
    const size_t zstride = (size_t)BATCH * 32;

    float h[8];
    #pragma unroll
    for (int j = 0; j < 8; j++) h[j] = 0.f;
    float cq = 0.f;
    float zcur = zp[0];

    #pragma unroll 1
    for (int t = 0; t < SEQ; t++) {
        float znext = (t + 1 < SEQ) ? zp[(size_t)(t + 1) * zstride] : 0.f;

        // recurrent dot — no shuffles, h is register-replicated
        float z = zcur;
        #pragma unroll
        for (int j = 0; j < 8; j++) z = fmaf(h[j], Whr[j], z);

        // qgate: prefix product of cos(z)*cos(theta) within 8-lane groups
        float cv = __cosf(z) * ctheta;
        #pragma unroll
        for (int d = 1; d < 8; d <<= 1) {
            float v = __shfl_up_sync(FULL, cv, d, 8);
            cv *= (q >= d) ? v : 1.0f;        // branch-free select
        }

        // nonlinearity: sigmoid(x) = 0.5*tanh(0.5x)+0.5 ; gate 2 uses tanh
        float arg = (g == 2) ? cv : 0.5f * cv;
        float th  = tanh_approx(arg);
        float a   = (g == 2) ? th : fmaf(0.5f, th, 0.5f);

        // gather f/i/u/o for this lane's qubit (4 independent shfls)
        float fv = __shfl_sync(FULL, a, q);
        float iv = __shfl_sync(FULL, a, 8 + q);
        float uv = __shfl_sync(FULL, a, 16 + q);
        float ov = __shfl_sync(FULL, a, 24 + q);

        cq = fmaf(fv, cq, iv * uv);
        float hnew = ov * tanh_approx(cq);

        // replicate h to all lanes (8 independent shfls, lanes 0..7 as source)
        #pragma unroll
        for (int j = 0; j < 8; j++) h[j] = __shfl_sync(FULL, hnew, j);

        if (lane < 8)
            stacked[((size_t)t * BATCH + b) * HDIM + q] = hnew;

        zcur = znext;
    }

    if (lane < 8) {
        hx_out[(size_t)b * HDIM + q] = h[q];
        cx_out[(size_t)b * HDIM + q] = cq;
    }
}

extern "C" void kernel_launch(void* const* d_in, const int* in_sizes, int n_in,
                              void* d_out, int out_size) {
    const float* inputs = (const float*)d_in[0];
    const float* Wf = (const float*)d_in[1];  const float* bf = (const float*)d_in[2];
    const float* Wi = (const float*)d_in[3];  const float* bi = (const float*)d_in[4];
    const float* Wu = (const float*)d_in[5];  const float* bu = (const float*)d_in[6];
    const float* Wo = (const float*)d_in[7];  const float* bo = (const float*)d_in[8];
    const float* pf  = (const float*)d_in[9];
    const float* pi_ = (const float*)d_in[10];
    const float* pu  = (const float*)d_in[11];
    const float* po  = (const float*)d_in[12];
    float* out = (float*)d_out;

    qlstm_gemm<<<2048, 256>>>(inputs, Wf, bf, Wi, bi, Wu, bu, Wo, bo);
    qlstm_recur<<<128, 128>>>(Wf, Wi, Wu, Wo, pf, pi_, pu, po, out);
}

// round 3
// speedup vs baseline: 3.3765x; 2.5504x over previous
#include <cuda_runtime.h>
#include <cstdint>

#define SEQ     256
#define BATCH   512
#define IN_DIM  256
#define HDIM    8
#define DIN     264          // IN_DIM + HDIM
#define NROWS   (SEQ * BATCH)

// Scratch: pre-activations from the input projection (bias folded in).
// Layout: zx[(t*BATCH + b)*32 + (g*8 + q)]
__device__ float g_zx[(size_t)NROWS * 32];

typedef unsigned long long ull;

__device__ __forceinline__ void ffma2(ull &d, ull a, ull b) {
    asm("fma.rn.f32x2 %0, %1, %2, %0;" : "+l"(d) : "l"(a), "l"(b));
}

__device__ __forceinline__ float tanh_approx(float x) {
    float y;
    asm("tanh.approx.f32 %0, %1;" : "=f"(y) : "f"(x));
    return y;
}

__device__ __forceinline__ void cpasync16(void* dst, const void* src) {
    unsigned ds = (unsigned)__cvta_generic_to_shared(dst);
    asm volatile("cp.async.cg.shared.global [%0], [%1], 16;" :: "r"(ds), "l"(src));
}
__device__ __forceinline__ void cp_commit() {
    asm volatile("cp.async.commit_group;");
}
template <int N>
__device__ __forceinline__ void cp_wait() {
    asm volatile("cp.async.wait_group %0;" :: "n"(N));
}

// ---------------------------------------------------------------------------
// Kernel A: zx = x @ Wx.T + b (x-part of all 4 gate projections).
//
// Block = 256 threads (8 warps), 128 rows/block, grid = 1024.
// lane = output o (all 32 outputs per warp); warp owns 16 rows.
// x tile in smem, read as FULL-WARP-BROADCAST LDS.128 (1 phase each): one
// 16B x read feeds 32 outputs x 4 k = 128 FMAs per warp.
// Weights staged once in smem with a 16B-slot XOR swizzle (lane-distinct rows
// would otherwise be 32-way bank conflicted); per k-chunk they are pulled
// into registers (8 LDS.128 at the 4-phase floor).
// Accumulators use packed fma.rn.f32x2.
// ---------------------------------------------------------------------------
#define KCH    32
#define NCHUNK 8

__global__ void __launch_bounds__(256)
qlstm_gemm(const float* __restrict__ x,
           const float* __restrict__ Wf, const float* __restrict__ bf,
           const float* __restrict__ Wi, const float* __restrict__ bi,
           const float* __restrict__ Wu, const float* __restrict__ bu,
           const float* __restrict__ Wo, const float* __restrict__ bo)
{
    __shared__ __align__(16) float w_s[32 * 256];      // 32KB, 16B-slot swizzled
    __shared__ __align__(16) float xs[2][128 * 32];    // 2 x 16KB x tile

    const int tid  = threadIdx.x;
    const int lane = tid & 31, warp = tid >> 5;
    const int row0   = blockIdx.x * 128;
    const int wrow0  = warp * 16;

    // Stage W x-part: 32 rows x 64 slots(16B) = 2048 slots, 8 per thread.
    #pragma unroll
    for (int i = 0; i < 8; i++) {
        int idx = tid + 256 * i;
        int o = idx >> 6, s = idx & 63;
        int sw = (s & ~7) | ((s & 7) ^ (o & 7));     // swizzle within 8-slot groups
        int g = o >> 3, q = o & 7;
        const float* base = (g == 0 ? Wf : (g == 1 ? Wi : (g == 2 ? Wu : Wo)));
        cpasync16(&w_s[o * 256 + sw * 4], base + q * DIN + s * 4);
    }

    // x chunk loader: 128 rows x 8 slots = 1024 slots, 4 per thread.
    auto load_x = [&](int kc, int buf) {
        #pragma unroll
        for (int i = 0; i < 4; i++) {
            int idx = tid + 256 * i;
            int r = idx >> 3, s = idx & 7;
            cpasync16(&xs[buf][r * 32 + s * 4],
                      x + (size_t)(row0 + r) * IN_DIM + kc * KCH + s * 4);
        }
    };

    load_x(0, 0);
    cp_commit();                     // group: {W, x-chunk0}

    ull acc[16];
    #pragma unroll
    for (int r = 0; r < 16; r++) acc[r] = 0ULL;

    #pragma unroll 1
    for (int kc = 0; kc < NCHUNK; kc++) {
        if (kc < NCHUNK - 1) { load_x(kc + 1, (kc + 1) & 1); cp_commit(); }
        if (kc < NCHUNK - 1) cp_wait<1>(); else cp_wait<0>();
        __syncthreads();

        // Pull this lane's weight chunk (32 floats) into registers.
        ull wreg[16];
        #pragma unroll
        for (int j = 0; j < 8; j++) {
            int s  = kc * 8 + j;
            int sw = (s & ~7) | ((s & 7) ^ (lane & 7));
            ulonglong2 wv = *reinterpret_cast<const ulonglong2*>(&w_s[lane * 256 + sw * 4]);
            wreg[2 * j] = wv.x; wreg[2 * j + 1] = wv.y;
        }

        const float* xb = xs[kc & 1];
        #pragma unroll
        for (int r = 0; r < 16; r++) {
            const ulonglong2* xp = reinterpret_cast<const ulonglong2*>(xb + (wrow0 + r) * 32);
            #pragma unroll
            for (int j = 0; j < 8; j++) {
                ulonglong2 xv = xp[j];                 // full-warp broadcast
                ffma2(acc[r], xv.x, wreg[2 * j]);
                ffma2(acc[r], xv.y, wreg[2 * j + 1]);
            }
        }
        __syncthreads();
    }

    const int g = lane >> 3, q = lane & 7;
    const float bias = (g == 0 ? bf : (g == 1 ? bi : (g == 2 ? bu : bo)))[q];

    #pragma unroll
    for (int r = 0; r < 16; r++) {
        float2 p = *reinterpret_cast<float2*>(&acc[r]);
        g_zx[(size_t)(row0 + wrow0 + r) * 32 + lane] = p.x + p.y + bias; // coalesced
    }
}

// ---------------------------------------------------------------------------
// Kernel B: the 256-step recurrence. One warp per batch element.
// Fully convergent loop (no divergent branches anywhere): since hnew and cq
// are replicated across the 4 gate-groups that share a qubit, ALL 32 lanes
// store (4 lanes write the identical value to the identical address). This
// lets the compiler keep the warp provably converged and drop per-shfl
// WARPSYNCs, which dominated the round-2 critical path.
// ---------------------------------------------------------------------------
__global__ void __launch_bounds__(128)
qlstm_recur(const float* __restrict__ Wf, const float* __restrict__ Wi,
            const float* __restrict__ Wu, const float* __restrict__ Wo,
            const float* __restrict__ pf, const float* __restrict__ pi_,
            const float* __restrict__ pu, const float* __restrict__ po,
            float* __restrict__ out)
{
    const unsigned FULL = 0xFFFFFFFFu;
    const int lane = threadIdx.x & 31;
    const int b    = blockIdx.x * (blockDim.x >> 5) + (threadIdx.x >> 5);
    const int g = lane >> 3, q = lane & 7;

    const float* W = (g == 0 ? Wf : (g == 1 ? Wi : (g == 2 ? Wu : Wo))) + q * DIN + IN_DIM;
    const float* p = (g == 0 ? pf : (g == 1 ? pi_ : (g == 2 ? pu : po)));

    float Whr[8];
    #pragma unroll
    for (int j = 0; j < 8; j++) Whr[j] = W[j];
    const float ctheta = __cosf(p[q]);

    float* stacked = out;
    float* hx_out  = out + (size_t)SEQ * BATCH * HDIM;
    float* cx_out  = hx_out + (size_t)BATCH * HDIM;

    const float* zp = g_zx + (size_t)b * 32 + lane;
    const size_t zstride = (size_t)BATCH * 32;

    float h[8];
    #pragma unroll
    for (int j = 0; j < 8; j++) h[j] = 0.f;
    float cq = 0.f;
    float zcur = zp[0];

    float* sp = stacked + (size_t)b * HDIM + q;
    const size_t sstride = (size_t)BATCH * HDIM;

    #pragma unroll 2
    for (int t = 0; t < SEQ; t++) {
        float znext = (t + 1 < SEQ) ? zp[(size_t)(t + 1) * zstride] : 0.f;

        // recurrent dot — h is register-replicated, pure FMA chain
        float z = zcur;
        #pragma unroll
        for (int j = 0; j < 8; j++) z = fmaf(h[j], Whr[j], z);

        // qgate: prefix product of cos(z)*cos(theta) within 8-lane groups
        float cv = __cosf(z) * ctheta;
        #pragma unroll
        for (int d = 1; d < 8; d <<= 1) {
            float v = __shfl_up_sync(FULL, cv, d, 8);
            cv *= (q >= d) ? v : 1.0f;        // FSEL, no branch
        }

        // sigmoid(x) = 0.5*tanh(0.5x)+0.5 ; gate 2 (u) uses plain tanh
        float arg = (g == 2) ? cv : 0.5f * cv;
        float th  = tanh_approx(arg);
        float a   = (g == 2) ? th : fmaf(0.5f, th, 0.5f);

        // gather f/i/u/o for this lane's qubit (4 independent shfls)
        float fv = __shfl_sync(FULL, a, q);
        float iv = __shfl_sync(FULL, a, 8 + q);
        float uv = __shfl_sync(FULL, a, 16 + q);
        float ov = __shfl_sync(FULL, a, 24 + q);

        cq = fmaf(fv, cq, iv * uv);
        float hnew = ov * tanh_approx(cq);   // identical across the 4 gate-groups

        // replicate h to all lanes (8 independent shfls)
        #pragma unroll
        for (int j = 0; j < 8; j++) h[j] = __shfl_sync(FULL, hnew, j);

        sp[(size_t)t * sstride] = hnew;      // ALL lanes store; 4x duplicate, same value

        zcur = znext;
    }

    hx_out[(size_t)b * HDIM + q] = h[q];     // convergent duplicate stores
    cx_out[(size_t)b * HDIM + q] = cq;
}

extern "C" void kernel_launch(void* const* d_in, const int* in_sizes, int n_in,
                              void* d_out, int out_size) {
    const float* inputs = (const float*)d_in[0];
    const float* Wf = (const float*)d_in[1];  const float* bf = (const float*)d_in[2];
    const float* Wi = (const float*)d_in[3];  const float* bi = (const float*)d_in[4];
    const float* Wu = (const float*)d_in[5];  const float* bu = (const float*)d_in[6];
    const float* Wo = (const float*)d_in[7];  const float* bo = (const float*)d_in[8];
    const float* pf  = (const float*)d_in[9];
    const float* pi_ = (const float*)d_in[10];
    const float* pu  = (const float*)d_in[11];
    const float* po  = (const float*)d_in[12];
    float* out = (float*)d_out;

    qlstm_gemm<<<1024, 256>>>(inputs, Wf, bf, Wi, bi, Wu, bu, Wo, bo);
    qlstm_recur<<<128, 128>>>(Wf, Wi, Wu, Wo, pf, pi_, pu, po, out);
}